// round 6
// baseline (speedup 1.0000x reference)
#include <cuda_runtime.h>
#include <math.h>
#include <stdint.h>

// ---------------- problem constants ----------------
#define HH 64
#define PP 64
#define NN 128
#define GG 8
#define KK 4
#define DM 4096
#define II 4096           // H*P
#define GN 1024           // G*N
#define CONVD 6144        // I + 2*GN
#define PROJ 10304        // I + CONVD + H
#define LSEQ 2048
#define BB 2
#define BT 4096           // B*L
#define GRPSZ 512         // I/G

#define OUT_ELEMS (4096*4096)
#define CS_ELEMS  (BB*CONVD*(KK-1))

#define LO_SCALE 252.0f
#define LO_INV   (1.0f / 252.0f)

// ---------------- scratch (device globals; no allocs allowed) ----------------
static __device__ float g_proj[(size_t)BT * PROJ];
static __device__ float g_xbc[(size_t)BT * CONVD];
static __device__ float g_dtp[BT * HH];
static __device__ float g_dA[BT * HH];
static __device__ float g_y[(size_t)BT * II];
static __device__ float g_yn[(size_t)BT * II];
static __device__ int8_t g_a8h[(size_t)BT * DM];
static __device__ int8_t g_a8l[(size_t)BT * DM];
static __device__ int8_t g_w8h[(size_t)PROJ * DM];
static __device__ int8_t g_w8l[(size_t)PROJ * DM];
static __device__ float g_rs_a[BT];     // per-row scale (A operand rows)
static __device__ float g_rs_b[PROJ];   // per-row scale (B operand rows)

__device__ __forceinline__ float silu_f(float x) {
    return x / (1.0f + __expf(-x));
}
__device__ __forceinline__ float softplus_f(float x) {
    return (x > 20.0f) ? x : log1pf(expf(x));
}

// ---------------- per-row absmax: one block per row, K=4096 ----------------
__global__ __launch_bounds__(256)
void rowmax_kernel(const float* __restrict__ src, float* __restrict__ scales) {
    const int row = blockIdx.x;
    const int tid = threadIdx.x;
    const float4* rp = (const float4*)(src + (size_t)row * 4096);
    float m = 0.f;
#pragma unroll
    for (int j = 0; j < 4; j++) {
        float4 v = rp[tid + j * 256];
        m = fmaxf(m, fmaxf(fmaxf(fabsf(v.x), fabsf(v.y)),
                           fmaxf(fabsf(v.z), fabsf(v.w))));
    }
#pragma unroll
    for (int o = 16; o; o >>= 1) m = fmaxf(m, __shfl_xor_sync(0xffffffffu, m, o));
    __shared__ float wm[8];
    if ((tid & 31) == 0) wm[tid >> 5] = m;
    __syncthreads();
    if (tid == 0) {
        float bm = wm[0];
#pragma unroll
        for (int w = 1; w < 8; w++) bm = fmaxf(bm, wm[w]);
        scales[row] = fmaxf(bm, 1e-30f) * (1.0f / 127.0f);   // s_row
    }
}

// ---------------- per-row 2-level quantize: x = s_row*(h + l/252) ----------------
__global__ void quant_kernel(const float* __restrict__ src,
                             int8_t* __restrict__ h8, int8_t* __restrict__ l8,
                             const float* __restrict__ scales, int n4) {
    int i = blockIdx.x * blockDim.x + threadIdx.x;
    if (i >= n4) return;
    int row = i >> 10;                 // K=4096 -> 1024 float4 per row
    float inv = 1.0f / scales[row];
    float4 v = ((const float4*)src)[i];
    float q0 = v.x * inv, q1 = v.y * inv, q2 = v.z * inv, q3 = v.w * inv;
    int h0 = __float2int_rn(q0), h1 = __float2int_rn(q1);
    int h2 = __float2int_rn(q2), h3 = __float2int_rn(q3);
    int l0 = __float2int_rn((q0 - (float)h0) * LO_SCALE);
    int l1 = __float2int_rn((q1 - (float)h1) * LO_SCALE);
    int l2 = __float2int_rn((q2 - (float)h2) * LO_SCALE);
    int l3 = __float2int_rn((q3 - (float)h3) * LO_SCALE);
    ((char4*)h8)[i] = make_char4((char)h0, (char)h1, (char)h2, (char)h3);
    ((char4*)l8)[i] = make_char4((char)l0, (char)l1, (char)l2, (char)l3);
}

// ---------------- int8 split tensor-core GEMM: C[M,N] = A[M,K] * B[N,K]^T ----------------
// CTA 128x128, 512 thr / 16 warps (4x4 of 32x32 warp tiles), BK=64.
// smem per stage: 4 planes (Ah, Al, Bh, Bl) of 128 rows x 80B (64B data + pad).
#define S8_STRIDE 80
#define PLANE_SZ  (128 * S8_STRIDE)     // 10240
#define STAGE_SZ  (4 * PLANE_SZ)        // 40960
#define GEMM8_SMEM (2 * STAGE_SZ)       // 81920

#define IMMA(d, a, b)                                                        \
    asm volatile(                                                            \
        "mma.sync.aligned.m16n8k32.row.col.s32.s8.s8.s32 "                   \
        "{%0,%1,%2,%3}, {%4,%5,%6,%7}, {%8,%9}, {%0,%1,%2,%3};\n"            \
        : "+r"((d)[0]), "+r"((d)[1]), "+r"((d)[2]), "+r"((d)[3])             \
        : "r"((a)[0]), "r"((a)[1]), "r"((a)[2]), "r"((a)[3]),                \
          "r"((b)[0]), "r"((b)[1]))

__device__ __forceinline__ uint32_t lds_u32(uint32_t a) {
    uint32_t v;
    asm volatile("ld.shared.b32 %0, [%1];" : "=r"(v) : "r"(a));
    return v;
}

__global__ __launch_bounds__(512, 1)
void gemm_s8_kernel(const int8_t* __restrict__ Ah, const int8_t* __restrict__ Al,
                    const int8_t* __restrict__ Bh, const int8_t* __restrict__ Bl,
                    const float* __restrict__ SA, const float* __restrict__ SB,
                    float* __restrict__ C, int M, int N, int K) {
    extern __shared__ __align__(16) int8_t sm8[];
    uint32_t smb;
    {
        uint64_t tmp;
        asm("cvta.to.shared.u64 %0, %1;" : "=l"(tmp) : "l"(sm8));
        smb = (uint32_t)tmp;
    }
    const int tid = threadIdx.x;
    const int warp = tid >> 5, lane = tid & 31;
    const int g = lane >> 2, tig = lane & 3;
    const int wm = (warp >> 2) * 32, wn = (warp & 3) * 32;
    const int row0 = blockIdx.y * 128, col0 = blockIdx.x * 128;

    // loader: thread -> (row r, 16B chunk c), all 4 planes
    const int lrr = tid >> 2, lc = tid & 3;
    const size_t goffA = (size_t)(row0 + lrr) * K + lc * 16;
    const size_t goffB = (size_t)(col0 + lrr) * K + lc * 16;
    const int bsz = ((col0 + lrr) < N) ? 16 : 0;
    const uint32_t soff = lrr * S8_STRIDE + lc * 16;

    int acc1[2][4][4], acc2[2][4][4];
#pragma unroll
    for (int mt = 0; mt < 2; mt++)
#pragma unroll
        for (int nt = 0; nt < 4; nt++)
#pragma unroll
            for (int i = 0; i < 4; i++) { acc1[mt][nt][i] = 0; acc2[mt][nt][i] = 0; }

    auto load_stage = [&](int buf, int kt) {
        const uint32_t base = smb + buf * STAGE_SZ + soff;
        asm volatile("cp.async.cg.shared.global [%0], [%1], 16;\n"
                     :: "r"(base), "l"(Ah + goffA + kt));
        asm volatile("cp.async.cg.shared.global [%0], [%1], 16;\n"
                     :: "r"(base + PLANE_SZ), "l"(Al + goffA + kt));
        asm volatile("cp.async.cg.shared.global [%0], [%1], 16, %2;\n"
                     :: "r"(base + 2 * PLANE_SZ), "l"(Bh + goffB + kt), "r"(bsz));
        asm volatile("cp.async.cg.shared.global [%0], [%1], 16, %2;\n"
                     :: "r"(base + 3 * PLANE_SZ), "l"(Bl + goffB + kt), "r"(bsz));
    };

    const int NK = K / 64;
    load_stage(0, 0);
    asm volatile("cp.async.commit_group;\n" ::: "memory");
    load_stage(1, 64);
    asm volatile("cp.async.commit_group;\n" ::: "memory");

    for (int it = 0; it < NK; it++) {
        asm volatile("cp.async.wait_group 1;\n" ::: "memory");
        __syncthreads();
        const uint32_t sb0 = smb + (it & 1) * STAGE_SZ;
#pragma unroll
        for (int s = 0; s < 2; s++) {
            const int ko = s * 32 + tig * 4;
            uint32_t ah[2][4], al[2][4], bh[4][2], bl[4][2];
#pragma unroll
            for (int mt = 0; mt < 2; mt++) {
                uint32_t a = sb0 + (wm + mt * 16 + g) * S8_STRIDE + ko;
                ah[mt][0] = lds_u32(a);
                ah[mt][1] = lds_u32(a + 8 * S8_STRIDE);
                ah[mt][2] = lds_u32(a + 16);
                ah[mt][3] = lds_u32(a + 8 * S8_STRIDE + 16);
                al[mt][0] = lds_u32(a + PLANE_SZ);
                al[mt][1] = lds_u32(a + PLANE_SZ + 8 * S8_STRIDE);
                al[mt][2] = lds_u32(a + PLANE_SZ + 16);
                al[mt][3] = lds_u32(a + PLANE_SZ + 8 * S8_STRIDE + 16);
            }
#pragma unroll
            for (int nt = 0; nt < 4; nt++) {
                uint32_t b = sb0 + 2 * PLANE_SZ + (wn + nt * 8 + g) * S8_STRIDE + ko;
                bh[nt][0] = lds_u32(b);
                bh[nt][1] = lds_u32(b + 16);
                bl[nt][0] = lds_u32(b + PLANE_SZ);
                bl[nt][1] = lds_u32(b + PLANE_SZ + 16);
            }
#pragma unroll
            for (int mt = 0; mt < 2; mt++)
#pragma unroll
                for (int nt = 0; nt < 4; nt++) {
                    IMMA(acc1[mt][nt], ah[mt], bh[nt]);
                    IMMA(acc2[mt][nt], ah[mt], bl[nt]);
                    IMMA(acc2[mt][nt], al[mt], bh[nt]);
                }
        }
        __syncthreads();
        if (it + 2 < NK) {
            load_stage(it & 1, (it + 2) * 64);
            asm volatile("cp.async.commit_group;\n" ::: "memory");
        } else {
            asm volatile("cp.async.commit_group;\n" ::: "memory");  // empty group keeps count
        }
    }

#pragma unroll
    for (int mt = 0; mt < 2; mt++) {
        int r = row0 + wm + mt * 16 + g;
        float sa0 = SA[r], sa1 = SA[r + 8];
#pragma unroll
        for (int nt = 0; nt < 4; nt++) {
            int cc = col0 + wn + nt * 8 + 2 * tig;
            if (cc < N) {
                float sb0f = SB[cc], sb1f = SB[cc + 1];
                float s00 = sa0 * sb0f, s01 = sa0 * sb1f;
                float s10 = sa1 * sb0f, s11 = sa1 * sb1f;
                float v0 = s00 * ((float)acc1[mt][nt][0] + (float)acc2[mt][nt][0] * LO_INV);
                float v1 = s01 * ((float)acc1[mt][nt][1] + (float)acc2[mt][nt][1] * LO_INV);
                float v2 = s10 * ((float)acc1[mt][nt][2] + (float)acc2[mt][nt][2] * LO_INV);
                float v3 = s11 * ((float)acc1[mt][nt][3] + (float)acc2[mt][nt][3] * LO_INV);
                float* p0 = C + (size_t)r * N + cc;
                float* p1 = C + (size_t)(r + 8) * N + cc;
                p0[0] = v0; p0[1] = v1;
                p1[0] = v2; p1[1] = v3;
            }
        }
    }
}

// ---------------- conv1d (depthwise, K=4, causal) + silu; 4 outputs/thread ----------------
__global__ void conv_kernel(const float* __restrict__ cw,
                            const float* __restrict__ cb,
                            float* __restrict__ conv_state) {
    int idx = blockIdx.x * blockDim.x + threadIdx.x;   // over (BT/4)*CONVD
    if (idx >= (BT / 4) * CONVD) return;
    int lb = idx / CONVD;
    int c  = idx - lb * CONVD;
    int b  = lb >> 9;                   // 512 l-blocks per batch
    int l0 = (lb & 511) * 4;

    const float w0 = cw[c * 4 + 0], w1 = cw[c * 4 + 1], w2 = cw[c * 4 + 2], w3 = cw[c * 4 + 3];
    const float bias = cb[c];
    const size_t colbase = (size_t)II + c;
    const size_t rowbase = ((size_t)b * LSEQ + l0) * PROJ + colbase;

    float xv[7];
#pragma unroll
    for (int j = 0; j < 3; j++)
        xv[j] = (l0 - 3 + j >= 0) ? g_proj[rowbase + (size_t)(j - 3) * PROJ] : 0.f;
#pragma unroll
    for (int j = 3; j < 7; j++)
        xv[j] = g_proj[rowbase + (size_t)(j - 3) * PROJ];

    size_t obase = ((size_t)b * LSEQ + l0) * CONVD + c;
#pragma unroll
    for (int j = 0; j < 4; j++) {
        float v = bias + xv[j] * w0 + xv[j + 1] * w1 + xv[j + 2] * w2 + xv[j + 3] * w3;
        g_xbc[obase + (size_t)j * CONVD] = silu_f(v);
        int l = l0 + j;
        if (l >= LSEQ - (KK - 1)) {
            conv_state[(b * CONVD + c) * (KK - 1) + (l - (LSEQ - (KK - 1)))] = xv[j + 3];
        }
    }
}

// ---------------- dt_p = softplus(dt + dt_bias); dA = exp(dt_p * -exp(A_log)) ----------------
__global__ void dt_kernel(const float* __restrict__ dt_bias,
                          const float* __restrict__ A_log) {
    int idx = blockIdx.x * blockDim.x + threadIdx.x;  // over BT*H
    if (idx >= BT * HH) return;
    int bt = idx >> 6;
    int h  = idx & 63;
    float dtv = g_proj[(size_t)bt * PROJ + (II + CONVD) + h] + dt_bias[h];
    float dtp = softplus_f(dtv);
    float A = -expf(A_log[h]);
    g_dtp[idx] = dtp;
    g_dA[idx] = expf(dtp * A);
}

// ---------------- sequential SSM scan: 1 CTA per (b,h) ----------------
__global__ __launch_bounds__(512, 1)
void scan_kernel(const float* __restrict__ Dv, float* __restrict__ final_state) {
    const int bh = blockIdx.x;
    const int b = bh >> 6, h = bh & 63;
    const int g = h >> 3;
    const int tid = threadIdx.x;
    const int p = tid >> 3;
    const int c = tid & 7;
    const int n0 = c * 16;

    __shared__ float xs[PP];
    __shared__ float Bsm[NN];
    __shared__ float Csm[NN];
    __shared__ float sc[2];

    float st[16];
#pragma unroll
    for (int i = 0; i < 16; i++) st[i] = 0.f;

    const float Dh = Dv[h];
    const size_t xcol = (size_t)h * PP;
    const size_t bcol = (size_t)II + (size_t)g * NN;
    const size_t ccol = (size_t)II + GN + (size_t)g * NN;

    float pref = 0.f, pdA = 0.f, pdtp = 0.f;
    auto load_t = [&](int t) {
        size_t row = ((size_t)b * LSEQ + t) * CONVD;
        if (tid < 64)        pref = g_xbc[row + xcol + tid];
        else if (tid < 192)  pref = g_xbc[row + bcol + (tid - 64)];
        else if (tid < 320)  pref = g_xbc[row + ccol + (tid - 192)];
        else if (tid == 320) {
            int i2 = (b * LSEQ + t) * HH + h;
            pdA = g_dA[i2];
            pdtp = g_dtp[i2];
        }
    };

    load_t(0);
    for (int t = 0; t < LSEQ; t++) {
        __syncthreads();
        if (tid < 64)        xs[tid] = pref;
        else if (tid < 192)  Bsm[tid - 64] = pref;
        else if (tid < 320)  Csm[tid - 192] = pref;
        else if (tid == 320) { sc[0] = pdA; sc[1] = pdtp; }
        __syncthreads();
        if (t + 1 < LSEQ) load_t(t + 1);

        float dAv = sc[0];
        float xp  = xs[p];
        float dtx = sc[1] * xp;
        float yp = 0.f;
#pragma unroll
        for (int i = 0; i < 16; i++) {
            float bn = Bsm[n0 + i];
            float cn = Csm[n0 + i];
            st[i] = fmaf(st[i], dAv, dtx * bn);
            yp = fmaf(st[i], cn, yp);
        }
        yp += __shfl_xor_sync(0xffffffffu, yp, 1);
        yp += __shfl_xor_sync(0xffffffffu, yp, 2);
        yp += __shfl_xor_sync(0xffffffffu, yp, 4);
        if (c == 0)
            g_y[((size_t)b * LSEQ + t) * II + (size_t)h * PP + p] = yp + Dh * xp;
    }

#pragma unroll
    for (int i = 0; i < 16; i++)
        final_state[((size_t)bh * PP + p) * NN + n0 + i] = st[i];
}

// ---------------- grouped RMS norm * norm_weight * silu(gate) ----------------
__global__ __launch_bounds__(512)
void norm_kernel(const float* __restrict__ nw) {
    const int row = blockIdx.x;
    const int tid = threadIdx.x;
    const float* yr = g_y + (size_t)row * II;

    float v[8];
    float ss = 0.f;
#pragma unroll
    for (int i = 0; i < 8; i++) {
        v[i] = yr[tid * 8 + i];
        ss = fmaf(v[i], v[i], ss);
    }
#pragma unroll
    for (int o = 16; o; o >>= 1) ss += __shfl_xor_sync(0xffffffffu, ss, o);

    __shared__ float wsum[16];
    if ((tid & 31) == 0) wsum[tid >> 5] = ss;
    __syncthreads();
    int gid = tid >> 6;
    float tot = wsum[gid * 2] + wsum[gid * 2 + 1];
    float rs = rsqrtf(tot * (1.0f / GRPSZ) + 1e-5f);

    const float* gr = g_proj + (size_t)row * PROJ;
    float* yo = g_yn + (size_t)row * II;
#pragma unroll
    for (int i = 0; i < 8; i++) {
        int col = tid * 8 + i;
        float gv = gr[col];
        yo[col] = v[i] * rs * nw[col] * silu_f(gv);
    }
}

// ---------------- launch ----------------
extern "C" void kernel_launch(void* const* d_in, const int* in_sizes, int n_in,
                              void* d_out, int out_size) {
    const float* hs        = (const float*)d_in[0];
    const float* in_proj_w = (const float*)d_in[1];
    const float* conv_w    = (const float*)d_in[2];
    const float* conv_b    = (const float*)d_in[3];
    const float* dt_bias   = (const float*)d_in[4];
    const float* A_log     = (const float*)d_in[5];
    const float* Dv        = (const float*)d_in[6];
    const float* norm_w    = (const float*)d_in[7];
    const float* out_w     = (const float*)d_in[8];

    float* out         = (float*)d_out;
    float* conv_state  = out + OUT_ELEMS;
    float* final_state = conv_state + CS_ELEMS;

    static int inited = 0;
    if (!inited) {
        cudaFuncSetAttribute(gemm_s8_kernel,
                             cudaFuncAttributeMaxDynamicSharedMemorySize, GEMM8_SMEM);
        inited = 1;
    }

    int8_t *pah, *pal, *pwh, *pwl;
    cudaGetSymbolAddress((void**)&pah, g_a8h);
    cudaGetSymbolAddress((void**)&pal, g_a8l);
    cudaGetSymbolAddress((void**)&pwh, g_w8h);
    cudaGetSymbolAddress((void**)&pwl, g_w8l);
    float *psa, *psb;
    cudaGetSymbolAddress((void**)&psa, g_rs_a);
    cudaGetSymbolAddress((void**)&psb, g_rs_b);
    float* pproj; cudaGetSymbolAddress((void**)&pproj, g_proj);
    float* pyn;   cudaGetSymbolAddress((void**)&pyn, g_yn);

    const int n4_hs = (BT * DM) / 4;
    const int n4_w1 = (PROJ * DM) / 4;
    const int n4_yn = (BT * II) / 4;
    const int n4_w2 = (DM * II) / 4;

    // 0. per-row scales + quantize in_proj operands
    rowmax_kernel<<<BT, 256>>>(hs, psa);
    rowmax_kernel<<<PROJ, 256>>>(in_proj_w, psb);
    quant_kernel<<<(n4_hs + 255) / 256, 256>>>(hs, pah, pal, psa, n4_hs);
    quant_kernel<<<(n4_w1 + 255) / 256, 256>>>(in_proj_w, pwh, pwl, psb, n4_w1);
    // 1. in_proj GEMM (int8 split tensor cores, per-row scales)
    {
        dim3 grid((PROJ + 127) / 128, BT / 128);
        gemm_s8_kernel<<<grid, 512, GEMM8_SMEM>>>(pah, pal, pwh, pwl, psa, psb,
                                                  pproj, BT, PROJ, DM);
    }
    // 2. conv + silu (+ conv_state)
    {
        int total = (BT / 4) * CONVD;
        conv_kernel<<<(total + 255) / 256, 256>>>(conv_w, conv_b, conv_state);
    }
    // 3. dt_p / dA
    {
        int total = BT * HH;
        dt_kernel<<<(total + 255) / 256, 256>>>(dt_bias, A_log);
    }
    // 4. sequential scan (+ final_state)
    scan_kernel<<<BB * HH, 512>>>(Dv, final_state);
    // 5. grouped RMS norm * gate -> fp32 yn
    norm_kernel<<<BT, 512>>>(norm_w);
    // 6. per-row scales + quantize out_proj operands, then out_proj GEMM -> d_out
    rowmax_kernel<<<BT, 256>>>(pyn, psa);
    rowmax_kernel<<<DM, 256>>>(out_w, psb);
    quant_kernel<<<(n4_yn + 255) / 256, 256>>>(pyn, pah, pal, psa, n4_yn);
    quant_kernel<<<(n4_w2 + 255) / 256, 256>>>(out_w, pwh, pwl, psb, n4_w2);
    {
        dim3 grid(DM / 128, BT / 128);
        gemm_s8_kernel<<<grid, 512, GEMM8_SMEM>>>(pah, pal, pwh, pwl, psa, psb,
                                                  out, BT, DM, II);
    }
}

// round 8
// speedup vs baseline: 1.6311x; 1.6311x over previous
#include <cuda_runtime.h>
#include <math.h>
#include <stdint.h>

// ---------------- problem constants ----------------
#define HH 64
#define PP 64
#define NN 128
#define GG 8
#define KK 4
#define DM 4096
#define II 4096           // H*P
#define GN 1024           // G*N
#define CONVD 6144        // I + 2*GN
#define PROJ 10304        // I + CONVD + H
#define LSEQ 2048
#define BB 2
#define BT 4096           // B*L
#define GRPSZ 512         // I/G

#define OUT_ELEMS (4096*4096)
#define CS_ELEMS  (BB*CONVD*(KK-1))

// ---------------- scratch (device globals; no allocs allowed) ----------------
static __device__ float g_proj[(size_t)BT * PROJ];
static __device__ float g_xbc[(size_t)BT * CONVD];
static __device__ float g_dtp[BT * HH];
static __device__ float g_dA[BT * HH];
static __device__ float g_y[(size_t)BT * II];
static __device__ float g_yn[(size_t)BT * II];

__device__ __forceinline__ float silu_f(float x) {
    return x / (1.0f + __expf(-x));
}
__device__ __forceinline__ float softplus_f(float x) {
    return (x > 20.0f) ? x : log1pf(expf(x));
}
__device__ __forceinline__ float tf32_rna(float x) {
    uint32_t r;
    asm("cvt.rna.tf32.f32 %0, %1;" : "=r"(r) : "f"(x));
    return __uint_as_float(r);
}

// ---------------- tensor-core tf32 GEMM: C[M,N] = A[M,K] * B[N,K]^T ----------------
// CTA 128x128, BK=16, 256 thr / 8 warps (2x4 of 64x32 warp tiles).
// Register-prefetch double-buffered smem, ONE __syncthreads per K-iter.
// Operands are tf32-RNA rounded in the loader (idempotent on pre-rounded data).
__global__ __launch_bounds__(256, 2)
void gemm_tc_kernel(const float* __restrict__ A, const float* __restrict__ B,
                    float* __restrict__ C, int M, int N, int K) {
    __shared__ __align__(16) float As[2][16][132];
    __shared__ __align__(16) float Bs[2][16][132];

    const int tid  = threadIdx.x;
    const int warp = tid >> 5, lane = tid & 31;
    const int g    = lane >> 2, tig = lane & 3;
    const int wm   = (warp >> 2) * 64;    // warp m offset (0 or 64)
    const int wn   = (warp & 3) * 32;     // warp n offset
    const int row0 = blockIdx.y * 128;
    const int col0 = blockIdx.x * 128;

    // loaders: 2 threads per row, 8 floats (2x float4) each
    const int lr = tid >> 1;
    const int lc = (tid & 1) * 8;
    const bool avalid = (row0 + lr) < M;
    const bool bvalid = (col0 + lr) < N;
    const float* Aptr = A + (size_t)(row0 + lr) * K + lc;
    const float* Bptr = B + (size_t)(col0 + lr) * K + lc;

    float4 pa0, pa1, pb0, pb1;
    auto fetch = [&](int kt) {
        if (avalid) {
            pa0 = *(const float4*)(Aptr + kt);
            pa1 = *(const float4*)(Aptr + kt + 4);
        } else {
            pa0 = make_float4(0.f,0.f,0.f,0.f); pa1 = pa0;
        }
        if (bvalid) {
            pb0 = *(const float4*)(Bptr + kt);
            pb1 = *(const float4*)(Bptr + kt + 4);
        } else {
            pb0 = make_float4(0.f,0.f,0.f,0.f); pb1 = pb0;
        }
    };
    auto store_stage = [&](int buf) {
        As[buf][lc+0][lr] = tf32_rna(pa0.x); As[buf][lc+1][lr] = tf32_rna(pa0.y);
        As[buf][lc+2][lr] = tf32_rna(pa0.z); As[buf][lc+3][lr] = tf32_rna(pa0.w);
        As[buf][lc+4][lr] = tf32_rna(pa1.x); As[buf][lc+5][lr] = tf32_rna(pa1.y);
        As[buf][lc+6][lr] = tf32_rna(pa1.z); As[buf][lc+7][lr] = tf32_rna(pa1.w);
        Bs[buf][lc+0][lr] = tf32_rna(pb0.x); Bs[buf][lc+1][lr] = tf32_rna(pb0.y);
        Bs[buf][lc+2][lr] = tf32_rna(pb0.z); Bs[buf][lc+3][lr] = tf32_rna(pb0.w);
        Bs[buf][lc+4][lr] = tf32_rna(pb1.x); Bs[buf][lc+5][lr] = tf32_rna(pb1.y);
        Bs[buf][lc+6][lr] = tf32_rna(pb1.z); Bs[buf][lc+7][lr] = tf32_rna(pb1.w);
    };

    float acc[4][4][4];
#pragma unroll
    for (int mt = 0; mt < 4; mt++)
#pragma unroll
        for (int nt = 0; nt < 4; nt++)
#pragma unroll
            for (int i = 0; i < 4; i++) acc[mt][nt][i] = 0.f;

    const int nk = K / 16;
    fetch(0);
    store_stage(0);
    __syncthreads();

    for (int it = 0; it < nk; it++) {
        if (it + 1 < nk) fetch((it + 1) * 16);
        const int buf = it & 1;
#pragma unroll
        for (int ks = 0; ks < 2; ks++) {
            const int k0 = ks * 8;
            uint32_t af[4][4], bf[4][2];
#pragma unroll
            for (int mt = 0; mt < 4; mt++) {
                int r = wm + mt * 16 + g;
                af[mt][0] = __float_as_uint(As[buf][k0 + tig][r]);
                af[mt][1] = __float_as_uint(As[buf][k0 + tig][r + 8]);
                af[mt][2] = __float_as_uint(As[buf][k0 + 4 + tig][r]);
                af[mt][3] = __float_as_uint(As[buf][k0 + 4 + tig][r + 8]);
            }
#pragma unroll
            for (int nt = 0; nt < 4; nt++) {
                int cc = wn + nt * 8 + g;
                bf[nt][0] = __float_as_uint(Bs[buf][k0 + tig][cc]);
                bf[nt][1] = __float_as_uint(Bs[buf][k0 + 4 + tig][cc]);
            }
#pragma unroll
            for (int mt = 0; mt < 4; mt++)
#pragma unroll
                for (int nt = 0; nt < 4; nt++)
                    asm volatile(
                        "mma.sync.aligned.m16n8k8.row.col.f32.tf32.tf32.f32 "
                        "{%0,%1,%2,%3}, {%4,%5,%6,%7}, {%8,%9}, {%0,%1,%2,%3};\n"
                        : "+f"(acc[mt][nt][0]), "+f"(acc[mt][nt][1]),
                          "+f"(acc[mt][nt][2]), "+f"(acc[mt][nt][3])
                        : "r"(af[mt][0]), "r"(af[mt][1]), "r"(af[mt][2]), "r"(af[mt][3]),
                          "r"(bf[nt][0]), "r"(bf[nt][1]));
        }
        if (it + 1 < nk) store_stage((it + 1) & 1);
        __syncthreads();
    }

#pragma unroll
    for (int mt = 0; mt < 4; mt++) {
        int r = row0 + wm + mt * 16 + g;
        if (r < M) {
#pragma unroll
            for (int nt = 0; nt < 4; nt++) {
                int cc = col0 + wn + nt * 8 + 2 * tig;
                if (cc < N) {   // N even, cc even -> cc+1 also valid
                    float* p0 = C + (size_t)r * N + cc;
                    float* p1 = C + (size_t)(r + 8) * N + cc;
                    p0[0] = acc[mt][nt][0]; p0[1] = acc[mt][nt][1];
                    p1[0] = acc[mt][nt][2]; p1[1] = acc[mt][nt][3];
                }
            }
        }
    }
}

// ---------------- conv1d (depthwise, K=4, causal) + silu; 4 outputs/thread ----------------
__global__ void conv_kernel(const float* __restrict__ cw,
                            const float* __restrict__ cb,
                            float* __restrict__ conv_state) {
    int idx = blockIdx.x * blockDim.x + threadIdx.x;   // over (BT/4)*CONVD
    if (idx >= (BT / 4) * CONVD) return;
    int lb = idx / CONVD;
    int c  = idx - lb * CONVD;
    int b  = lb >> 9;                   // 512 l-blocks per batch
    int l0 = (lb & 511) * 4;

    const float w0 = cw[c * 4 + 0], w1 = cw[c * 4 + 1], w2 = cw[c * 4 + 2], w3 = cw[c * 4 + 3];
    const float bias = cb[c];
    const size_t colbase = (size_t)II + c;
    const size_t rowbase = ((size_t)b * LSEQ + l0) * PROJ + colbase;

    float xv[7];
#pragma unroll
    for (int j = 0; j < 3; j++)
        xv[j] = (l0 - 3 + j >= 0) ? g_proj[rowbase + (size_t)(j - 3) * PROJ] : 0.f;
#pragma unroll
    for (int j = 3; j < 7; j++)
        xv[j] = g_proj[rowbase + (size_t)(j - 3) * PROJ];

    size_t obase = ((size_t)b * LSEQ + l0) * CONVD + c;
#pragma unroll
    for (int j = 0; j < 4; j++) {
        float v = bias + xv[j] * w0 + xv[j + 1] * w1 + xv[j + 2] * w2 + xv[j + 3] * w3;
        g_xbc[obase + (size_t)j * CONVD] = silu_f(v);
        int l = l0 + j;
        if (l >= LSEQ - (KK - 1)) {
            conv_state[(b * CONVD + c) * (KK - 1) + (l - (LSEQ - (KK - 1)))] = xv[j + 3];
        }
    }
}

// ---------------- dt_p = softplus(dt + dt_bias); dA = exp(dt_p * -exp(A_log)) ----------------
__global__ void dt_kernel(const float* __restrict__ dt_bias,
                          const float* __restrict__ A_log) {
    int idx = blockIdx.x * blockDim.x + threadIdx.x;  // over BT*H
    if (idx >= BT * HH) return;
    int bt = idx >> 6;
    int h  = idx & 63;
    float dtv = g_proj[(size_t)bt * PROJ + (II + CONVD) + h] + dt_bias[h];
    float dtp = softplus_f(dtv);
    float A = -expf(A_log[h]);
    g_dtp[idx] = dtp;
    g_dA[idx] = expf(dtp * A);
}

// ---------------- sequential SSM scan: 1 CTA per (b,h) ----------------
__global__ __launch_bounds__(512, 1)
void scan_kernel(const float* __restrict__ Dv, float* __restrict__ final_state) {
    const int bh = blockIdx.x;
    const int b = bh >> 6, h = bh & 63;
    const int g = h >> 3;
    const int tid = threadIdx.x;
    const int p = tid >> 3;
    const int c = tid & 7;
    const int n0 = c * 16;

    __shared__ float xs[PP];
    __shared__ float Bsm[NN];
    __shared__ float Csm[NN];
    __shared__ float sc[2];

    float st[16];
#pragma unroll
    for (int i = 0; i < 16; i++) st[i] = 0.f;

    const float Dh = Dv[h];
    const size_t xcol = (size_t)h * PP;
    const size_t bcol = (size_t)II + (size_t)g * NN;
    const size_t ccol = (size_t)II + GN + (size_t)g * NN;

    float pref = 0.f, pdA = 0.f, pdtp = 0.f;
    auto load_t = [&](int t) {
        size_t row = ((size_t)b * LSEQ + t) * CONVD;
        if (tid < 64)        pref = g_xbc[row + xcol + tid];
        else if (tid < 192)  pref = g_xbc[row + bcol + (tid - 64)];
        else if (tid < 320)  pref = g_xbc[row + ccol + (tid - 192)];
        else if (tid == 320) {
            int i2 = (b * LSEQ + t) * HH + h;
            pdA = g_dA[i2];
            pdtp = g_dtp[i2];
        }
    };

    load_t(0);
    for (int t = 0; t < LSEQ; t++) {
        __syncthreads();
        if (tid < 64)        xs[tid] = pref;
        else if (tid < 192)  Bsm[tid - 64] = pref;
        else if (tid < 320)  Csm[tid - 192] = pref;
        else if (tid == 320) { sc[0] = pdA; sc[1] = pdtp; }
        __syncthreads();
        if (t + 1 < LSEQ) load_t(t + 1);

        float dAv = sc[0];
        float xp  = xs[p];
        float dtx = sc[1] * xp;
        float yp0 = 0.f, yp1 = 0.f;
#pragma unroll
        for (int i = 0; i < 8; i++) {
            float bn = Bsm[n0 + i];
            float cn = Csm[n0 + i];
            st[i] = fmaf(st[i], dAv, dtx * bn);
            yp0 = fmaf(st[i], cn, yp0);
        }
#pragma unroll
        for (int i = 8; i < 16; i++) {
            float bn = Bsm[n0 + i];
            float cn = Csm[n0 + i];
            st[i] = fmaf(st[i], dAv, dtx * bn);
            yp1 = fmaf(st[i], cn, yp1);
        }
        float yp = yp0 + yp1;
        yp += __shfl_xor_sync(0xffffffffu, yp, 1);
        yp += __shfl_xor_sync(0xffffffffu, yp, 2);
        yp += __shfl_xor_sync(0xffffffffu, yp, 4);
        if (c == 0)
            g_y[((size_t)b * LSEQ + t) * II + (size_t)h * PP + p] = yp + Dh * xp;
    }

#pragma unroll
    for (int i = 0; i < 16; i++)
        final_state[((size_t)bh * PP + p) * NN + n0 + i] = st[i];
}

// ---------------- grouped RMS norm * norm_weight * silu(gate) ----------------
// Output is tf32-rounded (RNA); GEMM loader re-rounds (idempotent).
__global__ __launch_bounds__(512)
void norm_kernel(const float* __restrict__ nw) {
    const int row = blockIdx.x;
    const int tid = threadIdx.x;
    const float* yr = g_y + (size_t)row * II;

    float v[8];
    float ss = 0.f;
#pragma unroll
    for (int i = 0; i < 8; i++) {
        v[i] = yr[tid * 8 + i];
        ss = fmaf(v[i], v[i], ss);
    }
#pragma unroll
    for (int o = 16; o; o >>= 1) ss += __shfl_xor_sync(0xffffffffu, ss, o);

    __shared__ float wsum[16];
    if ((tid & 31) == 0) wsum[tid >> 5] = ss;
    __syncthreads();
    int gid = tid >> 6;
    float tot = wsum[gid * 2] + wsum[gid * 2 + 1];
    float rs = rsqrtf(tot * (1.0f / GRPSZ) + 1e-5f);

    const float* gr = g_proj + (size_t)row * PROJ;
    float* yo = g_yn + (size_t)row * II;
#pragma unroll
    for (int i = 0; i < 8; i++) {
        int col = tid * 8 + i;
        float gv = gr[col];
        yo[col] = tf32_rna(v[i] * rs * nw[col] * silu_f(gv));
    }
}

// ---------------- launch ----------------
extern "C" void kernel_launch(void* const* d_in, const int* in_sizes, int n_in,
                              void* d_out, int out_size) {
    const float* hs        = (const float*)d_in[0];
    const float* in_proj_w = (const float*)d_in[1];
    const float* conv_w    = (const float*)d_in[2];
    const float* conv_b    = (const float*)d_in[3];
    const float* dt_bias   = (const float*)d_in[4];
    const float* A_log     = (const float*)d_in[5];
    const float* Dv        = (const float*)d_in[6];
    const float* norm_w    = (const float*)d_in[7];
    const float* out_w     = (const float*)d_in[8];

    float* out         = (float*)d_out;
    float* conv_state  = out + OUT_ELEMS;
    float* final_state = conv_state + CS_ELEMS;

    float* pproj; cudaGetSymbolAddress((void**)&pproj, g_proj);
    float* pyn;   cudaGetSymbolAddress((void**)&pyn, g_yn);

    // 1. in_proj GEMM (tf32 tensor cores; operands rounded in-kernel)
    {
        dim3 grid((PROJ + 127) / 128, BT / 128);
        gemm_tc_kernel<<<grid, 256>>>(hs, in_proj_w, pproj, BT, PROJ, DM);
    }
    // 2. conv + silu (+ conv_state)
    {
        int total = (BT / 4) * CONVD;
        conv_kernel<<<(total + 255) / 256, 256>>>(conv_w, conv_b, conv_state);
    }
    // 3. dt_p / dA
    {
        int total = BT * HH;
        dt_kernel<<<(total + 255) / 256, 256>>>(dt_bias, A_log);
    }
    // 4. sequential scan (+ final_state)
    scan_kernel<<<BB * HH, 512>>>(Dv, final_state);
    // 5. grouped RMS norm * gate (tf32-rounded output)
    norm_kernel<<<BT, 512>>>(norm_w);
    // 6. out_proj GEMM -> d_out
    {
        dim3 grid(DM / 128, BT / 128);
        gemm_tc_kernel<<<grid, 256>>>(pyn, out_w, out, BT, DM, II);
    }
}